// round 1
// baseline (speedup 1.0000x reference)
#include <cuda_runtime.h>

// HeteroSTHN link-prediction head, fused single kernel.
// pred[n,t] = sum_h relu( h_s[n]·src_W[t,:,h] + src_b[t,h] + h_d[n]·dst_W[t,:,h] + dst_b[t,h] ) * out_W[t,h] + out_b[t]
// output[n]      = masked-max over t of pos pred (mask rows [0,E))
// output[E + n]  = masked-max over t of neg pred (mask rows [E,2E))
// S (neg_samples) == 1, so src encoding is shared between pos and neg edge n.

#define DD   200
#define HH   100
#define TT   8
#define BM   32
#define KC   100    // k-chunk depth (D = 2*KC)
#define HP   112    // padded H (7 * 16)
#define NJ   7      // h-values per thread (interleaved stride 16)
#define NEG_INF_F (-1e30f)

#define SMEM_BYTES ((3*BM*DD + 2*KC*HP) * 4)

__global__ __launch_bounds__(256, 1)
void sthn_fused_kernel(const float* __restrict__ h,
                       const float* __restrict__ srcW,
                       const float* __restrict__ srcb,
                       const float* __restrict__ dstW,
                       const float* __restrict__ dstb,
                       const float* __restrict__ outW,
                       const float* __restrict__ outb,
                       const int*   __restrict__ poss,
                       float* __restrict__ out,
                       int E)
{
    extern __shared__ float smem[];
    float* sA = smem;               // [3][BM][DD]  src / pos_dst / neg_dst tiles
    float* sW = smem + 3 * BM * DD; // [2][KC][HP]  srcW chunk / dstW chunk

    const int tid  = threadIdx.x;
    const int hg   = tid & 15;   // h-group lane (0..15)
    const int eg   = tid >> 4;   // edge group   (0..15)
    const int base = blockIdx.x * BM;

    // ---- stage the 3 x BM x D input tiles (float4, fully coalesced) ----
    for (int i = tid; i < 3 * BM * (DD / 4); i += 256) {
        const int m = i / (BM * (DD / 4));
        const int r = (i / (DD / 4)) % BM;
        const int q = i % (DD / 4);
        int row = base + r;
        if (row >= E) row = E - 1;                    // safety clamp (E divisible in practice)
        const float4 v = *reinterpret_cast<const float4*>(
            h + (size_t)(m * E + row) * DD + q * 4);
        *reinterpret_cast<float4*>(sA + (m * BM + r) * DD + q * 4) = v;
    }

    const int e0 = base + eg;
    const int e1 = base + eg + 16;

    // per-thread A row bases (two edges each, three matrices)
    const float* rowS0 = sA + (0 * BM + eg) * DD;
    const float* rowS1 = sA + (0 * BM + eg + 16) * DD;
    const float* rowP0 = sA + (1 * BM + eg) * DD;
    const float* rowP1 = sA + (1 * BM + eg + 16) * DD;
    const float* rowN0 = sA + (2 * BM + eg) * DD;
    const float* rowN1 = sA + (2 * BM + eg + 16) * DD;

    float bp0 = NEG_INF_F, bp1 = NEG_INF_F, bn0 = NEG_INF_F, bn1 = NEG_INF_F;
    int   ap0 = 0, ap1 = 0, an0 = 0, an1 = 0;

    for (int t = 0; t < TT; ++t) {
        float accS0[NJ], accS1[NJ], accP0[NJ], accP1[NJ], accN0[NJ], accN1[NJ];
        #pragma unroll
        for (int j = 0; j < NJ; ++j) {
            accS0[j] = 0.f; accS1[j] = 0.f;
            accP0[j] = 0.f; accP1[j] = 0.f;
            accN0[j] = 0.f; accN1[j] = 0.f;
        }

        #pragma unroll
        for (int kc = 0; kc < 2; ++kc) {
            __syncthreads();   // protect previous chunk's readers
            // ---- stage W chunk: src_W[t, kc*KC:(kc+1)*KC, :] and dst_W same ----
            {
                const float* WS = srcW + ((size_t)t * DD + kc * KC) * HH;
                const float* WD = dstW + ((size_t)t * DD + kc * KC) * HH;
                for (int i = tid; i < 2 * KC * (HP / 4); i += 256) {
                    const int m = i / (KC * (HP / 4));
                    const int d = (i / (HP / 4)) % KC;
                    const int s = i % (HP / 4);
                    float4 v = make_float4(0.f, 0.f, 0.f, 0.f);
                    if (s < HH / 4) {
                        const float* W = m ? WD : WS;
                        v = *reinterpret_cast<const float4*>(W + d * HH + s * 4);
                    }
                    *reinterpret_cast<float4*>(sW + (m * KC + d) * HP + s * 4) = v;
                }
            }
            __syncthreads();

            const float* As0 = rowS0 + kc * KC;
            const float* As1 = rowS1 + kc * KC;
            const float* Ap0 = rowP0 + kc * KC;
            const float* Ap1 = rowP1 + kc * KC;
            const float* An0 = rowN0 + kc * KC;
            const float* An1 = rowN1 + kc * KC;
            const float* Ws  = sW + hg;            // srcW chunk, column hg + 16j
            const float* Wd  = sW + KC * HP + hg;  // dstW chunk

            #pragma unroll 4
            for (int d = 0; d < KC; ++d) {
                const float a0s = As0[d];
                const float a1s = As1[d];
                const float a0p = Ap0[d];
                const float a1p = Ap1[d];
                const float a0n = An0[d];
                const float a1n = An1[d];
                const float* ws = Ws + d * HP;
                const float* wd = Wd + d * HP;
                #pragma unroll
                for (int j = 0; j < NJ; ++j) {
                    const float w_s = ws[16 * j];
                    const float w_d = wd[16 * j];
                    accS0[j] = fmaf(a0s, w_s, accS0[j]);
                    accS1[j] = fmaf(a1s, w_s, accS1[j]);
                    accP0[j] = fmaf(a0p, w_d, accP0[j]);
                    accP1[j] = fmaf(a1p, w_d, accP1[j]);
                    accN0[j] = fmaf(a0n, w_d, accN0[j]);
                    accN1[j] = fmaf(a1n, w_d, accN1[j]);
                }
            }
        }

        // ---- epilogue: relu + out_W dot (partial per thread over its 7 h's) ----
        float p0 = 0.f, p1 = 0.f, n0 = 0.f, n1 = 0.f;
        #pragma unroll
        for (int j = 0; j < NJ; ++j) {
            const int hh = hg + 16 * j;
            if (hh < HH) {
                const float b  = __ldg(srcb + t * HH + hh) + __ldg(dstb + t * HH + hh);
                const float ow = __ldg(outW + t * HH + hh);   // C == 1
                p0 += fmaxf(accS0[j] + accP0[j] + b, 0.f) * ow;
                p1 += fmaxf(accS1[j] + accP1[j] + b, 0.f) * ow;
                n0 += fmaxf(accS0[j] + accN0[j] + b, 0.f) * ow;
                n1 += fmaxf(accS1[j] + accN1[j] + b, 0.f) * ow;
            }
        }
        // butterfly reduce across the 16 hg lanes (offsets < 16 stay in-group)
        #pragma unroll
        for (int off = 8; off > 0; off >>= 1) {
            p0 += __shfl_xor_sync(0xffffffffu, p0, off);
            p1 += __shfl_xor_sync(0xffffffffu, p1, off);
            n0 += __shfl_xor_sync(0xffffffffu, n0, off);
            n1 += __shfl_xor_sync(0xffffffffu, n1, off);
        }

        const float ob = __ldg(outb + t);
        const int mp0 = __ldg(poss + (size_t)e0 * TT + t);
        const int mp1 = __ldg(poss + (size_t)e1 * TT + t);
        const int mn0 = __ldg(poss + ((size_t)E + e0) * TT + t);
        const int mn1 = __ldg(poss + ((size_t)E + e1) * TT + t);
        if (mp0) { bp0 = fmaxf(bp0, p0 + ob); ap0 = 1; }
        if (mp1) { bp1 = fmaxf(bp1, p1 + ob); ap1 = 1; }
        if (mn0) { bn0 = fmaxf(bn0, n0 + ob); an0 = 1; }
        if (mn1) { bn1 = fmaxf(bn1, n1 + ob); an1 = 1; }
    }

    if (hg == 0) {
        if (e0 < E) {
            out[e0]     = ap0 ? bp0 : 0.f;
            out[E + e0] = an0 ? bn0 : 0.f;
        }
        if (e1 < E) {
            out[e1]     = ap1 ? bp1 : 0.f;
            out[E + e1] = an1 ? bn1 : 0.f;
        }
    }
}

extern "C" void kernel_launch(void* const* d_in, const int* in_sizes, int n_in,
                              void* d_out, int out_size)
{
    const float* h    = (const float*)d_in[0];
    const float* srcW = (const float*)d_in[1];
    const float* srcb = (const float*)d_in[2];
    const float* dstW = (const float*)d_in[3];
    const float* dstb = (const float*)d_in[4];
    const float* outW = (const float*)d_in[5];
    const float* outb = (const float*)d_in[6];
    const int*   poss = (const int*)d_in[7];
    float* out = (float*)d_out;

    // S = 1, D = 200 -> h has E*(S+2) = 3E rows
    const int E = in_sizes[0] / (DD * 3);

    cudaFuncSetAttribute(sthn_fused_kernel,
                         cudaFuncAttributeMaxDynamicSharedMemorySize, SMEM_BYTES);

    const int grid = (E + BM - 1) / BM;
    sthn_fused_kernel<<<grid, 256, SMEM_BYTES>>>(h, srcW, srcb, dstW, dstb,
                                                 outW, outb, poss, out, E);
}

// round 2
// speedup vs baseline: 1.0009x; 1.0009x over previous
#include <cuda_runtime.h>

// HeteroSTHN link-prediction head, fused single kernel.
// pred[n,t] = sum_h relu( h_s[n]·src_W[t,:,h] + src_b[t,h] + h_d[n]·dst_W[t,:,h] + dst_b[t,h] ) * out_W[t,h] + out_b[t]
// output[n]      = masked-max over t of pos pred (mask rows [0,E))
// output[E + n]  = masked-max over t of neg pred (mask rows [E,2E))
// S (neg_samples) == 1, so src encoding is shared between pos and neg edge n.

#define DD   200
#define HH   100
#define TT   8
#define BM   32
#define KC   100    // k-chunk depth (D = 2*KC)
#define HP   112    // padded H (7 * 16)
#define NJ   7      // h-values per thread (interleaved stride 16)
#define NEG_INF_F (-1e30f)

#define SMEM_BYTES ((3*BM*DD + 2*KC*HP) * 4)

__global__ __launch_bounds__(256, 1)
void sthn_fused_kernel(const float* __restrict__ h,
                       const float* __restrict__ srcW,
                       const float* __restrict__ srcb,
                       const float* __restrict__ dstW,
                       const float* __restrict__ dstb,
                       const float* __restrict__ outW,
                       const float* __restrict__ outb,
                       const int*   __restrict__ poss,
                       float* __restrict__ out,
                       int E)
{
    extern __shared__ float smem[];
    float* sA = smem;               // [3][BM][DD]  src / pos_dst / neg_dst tiles
    float* sW = smem + 3 * BM * DD; // [2][KC][HP]  srcW chunk / dstW chunk

    const int tid  = threadIdx.x;
    const int hg   = tid & 15;   // h-group lane (0..15)
    const int eg   = tid >> 4;   // edge group   (0..15)
    const int base = blockIdx.x * BM;

    // ---- stage the 3 x BM x D input tiles (float4, fully coalesced) ----
    for (int i = tid; i < 3 * BM * (DD / 4); i += 256) {
        const int m = i / (BM * (DD / 4));
        const int r = (i / (DD / 4)) % BM;
        const int q = i % (DD / 4);
        int row = base + r;
        if (row >= E) row = E - 1;                    // safety clamp (E divisible in practice)
        const float4 v = *reinterpret_cast<const float4*>(
            h + (size_t)(m * E + row) * DD + q * 4);
        *reinterpret_cast<float4*>(sA + (m * BM + r) * DD + q * 4) = v;
    }

    const int e0 = base + eg;
    const int e1 = base + eg + 16;

    // per-thread A row bases (two edges each, three matrices)
    const float* rowS0 = sA + (0 * BM + eg) * DD;
    const float* rowS1 = sA + (0 * BM + eg + 16) * DD;
    const float* rowP0 = sA + (1 * BM + eg) * DD;
    const float* rowP1 = sA + (1 * BM + eg + 16) * DD;
    const float* rowN0 = sA + (2 * BM + eg) * DD;
    const float* rowN1 = sA + (2 * BM + eg + 16) * DD;

    float bp0 = NEG_INF_F, bp1 = NEG_INF_F, bn0 = NEG_INF_F, bn1 = NEG_INF_F;
    int   ap0 = 0, ap1 = 0, an0 = 0, an1 = 0;

    for (int t = 0; t < TT; ++t) {
        float accS0[NJ], accS1[NJ], accP0[NJ], accP1[NJ], accN0[NJ], accN1[NJ];
        #pragma unroll
        for (int j = 0; j < NJ; ++j) {
            accS0[j] = 0.f; accS1[j] = 0.f;
            accP0[j] = 0.f; accP1[j] = 0.f;
            accN0[j] = 0.f; accN1[j] = 0.f;
        }

        #pragma unroll
        for (int kc = 0; kc < 2; ++kc) {
            __syncthreads();   // protect previous chunk's readers
            // ---- stage W chunk: src_W[t, kc*KC:(kc+1)*KC, :] and dst_W same ----
            {
                const float* WS = srcW + ((size_t)t * DD + kc * KC) * HH;
                const float* WD = dstW + ((size_t)t * DD + kc * KC) * HH;
                for (int i = tid; i < 2 * KC * (HP / 4); i += 256) {
                    const int m = i / (KC * (HP / 4));
                    const int d = (i / (HP / 4)) % KC;
                    const int s = i % (HP / 4);
                    float4 v = make_float4(0.f, 0.f, 0.f, 0.f);
                    if (s < HH / 4) {
                        const float* W = m ? WD : WS;
                        v = *reinterpret_cast<const float4*>(W + d * HH + s * 4);
                    }
                    *reinterpret_cast<float4*>(sW + (m * KC + d) * HP + s * 4) = v;
                }
            }
            __syncthreads();

            const float* As0 = rowS0 + kc * KC;
            const float* As1 = rowS1 + kc * KC;
            const float* Ap0 = rowP0 + kc * KC;
            const float* Ap1 = rowP1 + kc * KC;
            const float* An0 = rowN0 + kc * KC;
            const float* An1 = rowN1 + kc * KC;
            const float* Ws  = sW + hg;            // srcW chunk, column hg + 16j
            const float* Wd  = sW + KC * HP + hg;  // dstW chunk

            #pragma unroll 4
            for (int d = 0; d < KC; ++d) {
                const float a0s = As0[d];
                const float a1s = As1[d];
                const float a0p = Ap0[d];
                const float a1p = Ap1[d];
                const float a0n = An0[d];
                const float a1n = An1[d];
                const float* ws = Ws + d * HP;
                const float* wd = Wd + d * HP;
                #pragma unroll
                for (int j = 0; j < NJ; ++j) {
                    const float w_s = ws[16 * j];
                    const float w_d = wd[16 * j];
                    accS0[j] = fmaf(a0s, w_s, accS0[j]);
                    accS1[j] = fmaf(a1s, w_s, accS1[j]);
                    accP0[j] = fmaf(a0p, w_d, accP0[j]);
                    accP1[j] = fmaf(a1p, w_d, accP1[j]);
                    accN0[j] = fmaf(a0n, w_d, accN0[j]);
                    accN1[j] = fmaf(a1n, w_d, accN1[j]);
                }
            }
        }

        // ---- epilogue: relu + out_W dot (partial per thread over its 7 h's) ----
        float p0 = 0.f, p1 = 0.f, n0 = 0.f, n1 = 0.f;
        #pragma unroll
        for (int j = 0; j < NJ; ++j) {
            const int hh = hg + 16 * j;
            if (hh < HH) {
                const float b  = __ldg(srcb + t * HH + hh) + __ldg(dstb + t * HH + hh);
                const float ow = __ldg(outW + t * HH + hh);   // C == 1
                p0 += fmaxf(accS0[j] + accP0[j] + b, 0.f) * ow;
                p1 += fmaxf(accS1[j] + accP1[j] + b, 0.f) * ow;
                n0 += fmaxf(accS0[j] + accN0[j] + b, 0.f) * ow;
                n1 += fmaxf(accS1[j] + accN1[j] + b, 0.f) * ow;
            }
        }
        // butterfly reduce across the 16 hg lanes (offsets < 16 stay in-group)
        #pragma unroll
        for (int off = 8; off > 0; off >>= 1) {
            p0 += __shfl_xor_sync(0xffffffffu, p0, off);
            p1 += __shfl_xor_sync(0xffffffffu, p1, off);
            n0 += __shfl_xor_sync(0xffffffffu, n0, off);
            n1 += __shfl_xor_sync(0xffffffffu, n1, off);
        }

        const float ob = __ldg(outb + t);
        const int mp0 = __ldg(poss + (size_t)e0 * TT + t);
        const int mp1 = __ldg(poss + (size_t)e1 * TT + t);
        const int mn0 = __ldg(poss + ((size_t)E + e0) * TT + t);
        const int mn1 = __ldg(poss + ((size_t)E + e1) * TT + t);
        if (mp0) { bp0 = fmaxf(bp0, p0 + ob); ap0 = 1; }
        if (mp1) { bp1 = fmaxf(bp1, p1 + ob); ap1 = 1; }
        if (mn0) { bn0 = fmaxf(bn0, n0 + ob); an0 = 1; }
        if (mn1) { bn1 = fmaxf(bn1, n1 + ob); an1 = 1; }
    }

    if (hg == 0) {
        if (e0 < E) {
            out[e0]     = ap0 ? bp0 : 0.f;
            out[E + e0] = an0 ? bn0 : 0.f;
        }
        if (e1 < E) {
            out[e1]     = ap1 ? bp1 : 0.f;
            out[E + e1] = an1 ? bn1 : 0.f;
        }
    }
}

extern "C" void kernel_launch(void* const* d_in, const int* in_sizes, int n_in,
                              void* d_out, int out_size)
{
    const float* h    = (const float*)d_in[0];
    const float* srcW = (const float*)d_in[1];
    const float* srcb = (const float*)d_in[2];
    const float* dstW = (const float*)d_in[3];
    const float* dstb = (const float*)d_in[4];
    const float* outW = (const float*)d_in[5];
    const float* outb = (const float*)d_in[6];
    const int*   poss = (const int*)d_in[7];
    float* out = (float*)d_out;

    // S = 1, D = 200 -> h has E*(S+2) = 3E rows
    const int E = in_sizes[0] / (DD * 3);

    cudaFuncSetAttribute(sthn_fused_kernel,
                         cudaFuncAttributeMaxDynamicSharedMemorySize, SMEM_BYTES);

    const int grid = (E + BM - 1) / BM;
    sthn_fused_kernel<<<grid, 256, SMEM_BYTES>>>(h, srcW, srcb, dstW, dstb,
                                                 outW, outb, poss, out, E);
}

// round 4
// speedup vs baseline: 2.6498x; 2.6474x over previous
#include <cuda_runtime.h>
#include <cuda_bf16.h>
#include <cstdint>

// ---------------------------------------------------------------------------
// HeteroSTHN link-prediction head via mma.sync (HMMA bf16, 3-pass compensated
// split). Plain sm_103 PTX target => no tcgen05; ldmatrix + mma.sync only.
//
//   enc_src = h_src @ src_W + src_b   (bias folded as K row 200, A=1.0)
//   enc_dst = h_dst @ dst_W + dst_b
//   pred[n,t] = relu(enc_src + enc_dst) @ out_W[t] + out_b[t]
//   out[n] = masked max over t (pos);  out[E+n] = masked max over t (neg)
//
// bf16 split x = hi + lo;  P = Ahi*Bhi + Ahi*Blo + Alo*Bhi  (err ~2^-16)
// ---------------------------------------------------------------------------

#define TT    8
#define DDIM  200
#define HDIM  100
#define KPAD  208           // 13 ksteps of 16 (k=200 is the bias row)
#define NPAD  112           // 14 n-frags of 8
#define BM    128
#define EMAX  65536

__device__ __align__(16) uint16_t g_Ahi[(size_t)3 * EMAX * KPAD];
__device__ __align__(16) uint16_t g_Alo[(size_t)3 * EMAX * KPAD];
__device__ __align__(16) uint16_t g_B[(size_t)4 * TT * KPAD * NPAD];

// ---- smem layout (bytes) ----
#define OFF_OW  0                       // 8 * 112 floats = 3584
#define OFF_A   3584
#define A_ROWB  144                     // 64 k * 2B = 128, +16 pad (LDSM conflict-free)
#define A_SPL   (384 * A_ROWB)          // 55296 per split
#define OFF_B   (OFF_A + 2 * A_SPL)     // 114176
#define B_ROWB  240                     // 112 n * 2B = 224, +16 pad
#define B_SET   (64 * B_ROWB)           // 15360 per (wm,split)
#define SMEM_TOTAL (OFF_B + 4 * B_SET)  // 175616

// ---------------- asm helpers ----------------
__device__ __forceinline__ uint32_t smem_u32(const void* p) {
    uint32_t a;
    asm("{ .reg .u64 t; cvta.to.shared.u64 t, %1; cvt.u32.u64 %0, t; }" : "=r"(a) : "l"(p));
    return a;
}

#define LDSM_X4(R0,R1,R2,R3,ADDR) \
    asm volatile("ldmatrix.sync.aligned.m8n8.x4.shared.b16 {%0,%1,%2,%3}, [%4];" \
        : "=r"(R0), "=r"(R1), "=r"(R2), "=r"(R3) : "r"(ADDR))

#define LDSM_X4T(R0,R1,R2,R3,ADDR) \
    asm volatile("ldmatrix.sync.aligned.m8n8.x4.trans.shared.b16 {%0,%1,%2,%3}, [%4];" \
        : "=r"(R0), "=r"(R1), "=r"(R2), "=r"(R3) : "r"(ADDR))

#define MMA4(C, A, B0, B1) \
    asm volatile("mma.sync.aligned.m16n8k16.row.col.f32.bf16.bf16.f32 " \
        "{%0,%1,%2,%3}, {%4,%5,%6,%7}, {%8,%9}, {%0,%1,%2,%3};" \
        : "+f"((C)[0]), "+f"((C)[1]), "+f"((C)[2]), "+f"((C)[3]) \
        : "r"((A)[0]), "r"((A)[1]), "r"((A)[2]), "r"((A)[3]), "r"(B0), "r"(B1))

// ---------------------------------------------------------------------------
// prep A: h (fp32, 3E x 200) -> bf16 hi/lo, K padded to 208 (k200 = 1.0)
// ---------------------------------------------------------------------------
__global__ void prepA_kernel(const float* __restrict__ h, int E) {
    const long gid = (long)blockIdx.x * 256 + threadIdx.x;
    const long total = (long)3 * E * 26;          // 26 groups of 8 per row
    if (gid >= total) return;
    const int  q   = (int)(gid % 26);
    const long row = gid / 26;
    const int  k0  = q * 8;
    const float* hr = h + row * DDIM;

    __align__(16) uint16_t hb[8], lb[8];
    #pragma unroll
    for (int j = 0; j < 8; ++j) {
        const int k = k0 + j;
        const float v = (k < DDIM) ? hr[k] : (k == DDIM ? 1.0f : 0.0f);
        __nv_bfloat16 hi = __float2bfloat16(v);
        const float lo = v - __bfloat162float(hi);
        __nv_bfloat16 lob = __float2bfloat16(lo);
        hb[j] = *reinterpret_cast<uint16_t*>(&hi);
        lb[j] = *reinterpret_cast<uint16_t*>(&lob);
    }
    const size_t o = (size_t)row * KPAD + k0;
    *reinterpret_cast<uint4*>(g_Ahi + o) = *reinterpret_cast<uint4*>(hb);
    *reinterpret_cast<uint4*>(g_Alo + o) = *reinterpret_cast<uint4*>(lb);
}

// ---------------------------------------------------------------------------
// prep B: src_W/dst_W (T,200,100) + biases -> g_B[(wm*2+split)][t][208][112]
// k-major rows of n (for ldmatrix.trans); bias at k==200; zero padding
// ---------------------------------------------------------------------------
__global__ void prepB_kernel(const float* __restrict__ srcW, const float* __restrict__ srcb,
                             const float* __restrict__ dstW, const float* __restrict__ dstb) {
    const int gid = blockIdx.x * 256 + threadIdx.x;
    const int total = 2 * TT * KPAD * 14;
    if (gid >= total) return;
    const int nb = gid % 14;
    int rr = gid / 14;
    const int k = rr % KPAD;  rr /= KPAD;
    const int t = rr % TT;
    const int wm = rr / TT;

    const float* W  = wm ? dstW : srcW;
    const float* bb = wm ? dstb : srcb;

    __align__(16) uint16_t hb[8], lb[8];
    #pragma unroll
    for (int j = 0; j < 8; ++j) {
        const int n = nb * 8 + j;
        float v = 0.0f;
        if (n < HDIM) {
            if (k < DDIM)       v = W[((size_t)t * DDIM + k) * HDIM + n];
            else if (k == DDIM) v = bb[t * HDIM + n];
        }
        __nv_bfloat16 hi = __float2bfloat16(v);
        const float lo = v - __bfloat162float(hi);
        __nv_bfloat16 lob = __float2bfloat16(lo);
        hb[j] = *reinterpret_cast<uint16_t*>(&hi);
        lb[j] = *reinterpret_cast<uint16_t*>(&lob);
    }
    const size_t ohi = (((size_t)(wm * 2 + 0) * TT + t) * KPAD + k) * NPAD + nb * 8;
    const size_t olo = (((size_t)(wm * 2 + 1) * TT + t) * KPAD + k) * NPAD + nb * 8;
    *reinterpret_cast<uint4*>(g_B + ohi) = *reinterpret_cast<uint4*>(hb);
    *reinterpret_cast<uint4*>(g_B + olo) = *reinterpret_cast<uint4*>(lb);
}

// ---------------------------------------------------------------------------
// main kernel: per block 128 edges; warp w owns 16 edges across src/pos/neg
// ---------------------------------------------------------------------------
__global__ __launch_bounds__(256, 1)
void sthn_hmma_kernel(const float* __restrict__ outW, const float* __restrict__ outb,
                      const int* __restrict__ poss, float* __restrict__ out, int E)
{
    extern __shared__ char smem[];
    const uint32_t sb = smem_u32(smem);
    const int tid = threadIdx.x;
    const int w = tid >> 5, l = tid & 31;
    const int blk = blockIdx.x;

    // stage out_W (zero-padded), consumed after first __syncthreads
    {
        float* sOW = reinterpret_cast<float*>(smem + OFF_OW);
        for (int i = tid; i < TT * NPAD; i += 256) {
            const int t = i / NPAD, n = i % NPAD;
            sOW[i] = (n < HDIM) ? outW[t * HDIM + n] : 0.0f;
        }
    }

    const int lr = l & 15, lc = l >> 4;            // ldmatrix lane addressing
    const int qr = l >> 2, qc = l & 3;             // C-fragment row/col in quad
    const uint32_t a_lane = (uint32_t)((w * 16 + lr) * A_ROWB + lc * 16);
    const uint32_t b_lane = (uint32_t)(lr * B_ROWB + lc * 16);

    float bests[4] = {-1e30f, -1e30f, -1e30f, -1e30f};
    int   anys[4]  = {0, 0, 0, 0};

    for (int t = 0; t < TT; ++t) {
        float C[3][14][4];
        #pragma unroll
        for (int m = 0; m < 3; ++m)
            #pragma unroll
            for (int nf = 0; nf < 14; ++nf)
                #pragma unroll
                for (int j = 0; j < 4; ++j) C[m][nf][j] = 0.0f;

        for (int chunk = 0; chunk < 4; ++chunk) {
            __syncthreads();
            // ---- stage A chunk: 2 splits x 384 rows x 64 k (padded rows) ----
            for (int i = tid; i < 6144; i += 256) {
                const int sp = i / 3072, rem = i % 3072;
                const int row = rem >> 3, q = rem & 7;
                const int m = row >> 7, r = row & 127;
                const int kk = chunk * 64 + q * 8;
                uint4 v = make_uint4(0, 0, 0, 0);
                if (kk < KPAD) {
                    const uint16_t* src = (sp ? g_Alo : g_Ahi)
                        + ((size_t)m * E + (size_t)blk * BM + r) * KPAD + kk;
                    v = *reinterpret_cast<const uint4*>(src);
                }
                *reinterpret_cast<uint4*>(smem + OFF_A + sp * A_SPL + row * A_ROWB + q * 16) = v;
            }
            // ---- stage B chunk: 4 sets x 64 k-rows x 112 n ----
            for (int i = tid; i < 3584; i += 256) {
                const int set = i / 896, rem = i % 896;
                const int kr = rem / 14, q = rem % 14;
                const int kk = chunk * 64 + kr;
                uint4 v = make_uint4(0, 0, 0, 0);
                if (kk < KPAD) {
                    const uint16_t* src = g_B
                        + (((size_t)set * TT + t) * KPAD + kk) * NPAD + q * 8;
                    v = *reinterpret_cast<const uint4*>(src);
                }
                *reinterpret_cast<uint4*>(smem + OFF_B + set * B_SET + kr * B_ROWB + q * 16) = v;
            }
            __syncthreads();

            const int nk = (chunk < 3) ? 4 : 1;
            for (int ks = 0; ks < nk; ++ks) {
                const uint32_t k0 = (uint32_t)ks * 16;
                uint32_t Ah[3][4], Al[3][4];
                #pragma unroll
                for (int m = 0; m < 3; ++m) {
                    const uint32_t aa = sb + OFF_A + (uint32_t)(m * 128 * A_ROWB)
                                        + a_lane + k0 * 2;
                    LDSM_X4(Ah[m][0], Ah[m][1], Ah[m][2], Ah[m][3], aa);
                    LDSM_X4(Al[m][0], Al[m][1], Al[m][2], Al[m][3], aa + A_SPL);
                }
                #pragma unroll
                for (int wm = 0; wm < 2; ++wm) {
                    #pragma unroll
                    for (int nf2 = 0; nf2 < 7; ++nf2) {
                        const uint32_t ba = sb + OFF_B + (uint32_t)(wm * 2 * B_SET)
                                            + k0 * B_ROWB + b_lane + (uint32_t)nf2 * 32;
                        uint32_t bh[4], bl[4];
                        LDSM_X4T(bh[0], bh[1], bh[2], bh[3], ba);
                        LDSM_X4T(bl[0], bl[1], bl[2], bl[3], ba + B_SET);
                        if (wm == 0) {
                            MMA4(C[0][2*nf2],   Ah[0], bh[0], bh[1]);
                            MMA4(C[0][2*nf2+1], Ah[0], bh[2], bh[3]);
                            MMA4(C[0][2*nf2],   Al[0], bh[0], bh[1]);
                            MMA4(C[0][2*nf2+1], Al[0], bh[2], bh[3]);
                            MMA4(C[0][2*nf2],   Ah[0], bl[0], bl[1]);
                            MMA4(C[0][2*nf2+1], Ah[0], bl[2], bl[3]);
                        } else {
                            #pragma unroll
                            for (int m = 1; m < 3; ++m) {
                                MMA4(C[m][2*nf2],   Ah[m], bh[0], bh[1]);
                                MMA4(C[m][2*nf2+1], Ah[m], bh[2], bh[3]);
                                MMA4(C[m][2*nf2],   Al[m], bh[0], bh[1]);
                                MMA4(C[m][2*nf2+1], Al[m], bh[2], bh[3]);
                                MMA4(C[m][2*nf2],   Ah[m], bl[0], bl[1]);
                                MMA4(C[m][2*nf2+1], Ah[m], bl[2], bl[3]);
                            }
                        }
                    }
                }
            }
        }

        // ---- epilogue: relu(src+dst) . out_W, quad reduce, masked max ----
        float pl = 0.f, ph = 0.f, nl = 0.f, nh = 0.f;
        const float* ow = reinterpret_cast<const float*>(smem + OFF_OW) + t * NPAD;
        const int col0 = 2 * qc;
        #pragma unroll
        for (int nf = 0; nf < 14; ++nf) {
            const float ow0 = ow[nf * 8 + col0];
            const float ow1 = ow[nf * 8 + col0 + 1];
            pl += fmaxf(C[0][nf][0] + C[1][nf][0], 0.f) * ow0
                + fmaxf(C[0][nf][1] + C[1][nf][1], 0.f) * ow1;
            ph += fmaxf(C[0][nf][2] + C[1][nf][2], 0.f) * ow0
                + fmaxf(C[0][nf][3] + C[1][nf][3], 0.f) * ow1;
            nl += fmaxf(C[0][nf][0] + C[2][nf][0], 0.f) * ow0
                + fmaxf(C[0][nf][1] + C[2][nf][1], 0.f) * ow1;
            nh += fmaxf(C[0][nf][2] + C[2][nf][2], 0.f) * ow0
                + fmaxf(C[0][nf][3] + C[2][nf][3], 0.f) * ow1;
        }
        #pragma unroll
        for (int off = 1; off < 4; off <<= 1) {
            pl += __shfl_xor_sync(0xffffffffu, pl, off);
            ph += __shfl_xor_sync(0xffffffffu, ph, off);
            nl += __shfl_xor_sync(0xffffffffu, nl, off);
            nh += __shfl_xor_sync(0xffffffffu, nh, off);
        }

        const float ob = __ldg(outb + t);
        const int e_lo = blk * BM + w * 16 + qr;
        const int e_hi = e_lo + 8;
        const int mpl = __ldg(poss + (size_t)e_lo * TT + t);
        const int mph = __ldg(poss + (size_t)e_hi * TT + t);
        const int mnl = __ldg(poss + ((size_t)E + e_lo) * TT + t);
        const int mnh = __ldg(poss + ((size_t)E + e_hi) * TT + t);
        if (mpl) { bests[0] = fmaxf(bests[0], pl + ob); anys[0] = 1; }
        if (mph) { bests[1] = fmaxf(bests[1], ph + ob); anys[1] = 1; }
        if (mnl) { bests[2] = fmaxf(bests[2], nl + ob); anys[2] = 1; }
        if (mnh) { bests[3] = fmaxf(bests[3], nh + ob); anys[3] = 1; }
    }

    if (qc == 0) {
        const int e_lo = blk * BM + w * 16 + qr;
        const int e_hi = e_lo + 8;
        out[e_lo]     = anys[0] ? bests[0] : 0.0f;
        out[e_hi]     = anys[1] ? bests[1] : 0.0f;
        out[E + e_lo] = anys[2] ? bests[2] : 0.0f;
        out[E + e_hi] = anys[3] ? bests[3] : 0.0f;
    }
}

// ---------------------------------------------------------------------------
extern "C" void kernel_launch(void* const* d_in, const int* in_sizes, int n_in,
                              void* d_out, int out_size)
{
    const float* h    = (const float*)d_in[0];
    const float* srcW = (const float*)d_in[1];
    const float* srcb = (const float*)d_in[2];
    const float* dstW = (const float*)d_in[3];
    const float* dstb = (const float*)d_in[4];
    const float* outW = (const float*)d_in[5];
    const float* outb = (const float*)d_in[6];
    const int*   poss = (const int*)d_in[7];
    float* out = (float*)d_out;

    const int E = in_sizes[0] / (DDIM * 3);

    {
        const long totalA = (long)3 * E * 26;
        prepA_kernel<<<(int)((totalA + 255) / 256), 256>>>(h, E);
    }
    {
        const int totalB = 2 * TT * KPAD * 14;
        prepB_kernel<<<(totalB + 255) / 256, 256>>>(srcW, srcb, dstW, dstb);
    }

    cudaFuncSetAttribute(sthn_hmma_kernel,
                         cudaFuncAttributeMaxDynamicSharedMemorySize, SMEM_TOTAL);
    sthn_hmma_kernel<<<E / BM, 256, SMEM_TOTAL>>>(outW, outb, poss, out, E);
}

// round 6
// speedup vs baseline: 5.1417x; 1.9404x over previous
#include <cuda_runtime.h>
#include <cuda_fp16.h>
#include <cstdint>

// ---------------------------------------------------------------------------
// HeteroSTHN link-prediction head via mma.sync HMMA fp16 (single pass,
// fp32 accumulate). Plain sm_103 PTX target (no tcgen05).
//
//   enc_src = h_src @ src_W + src_b   (bias folded as K row 200, A=1.0)
//   enc_dst = h_dst @ dst_W + dst_b
//   pred[n,t] = relu(enc_src + enc_dst) @ out_W[t] + out_b[t]
//   out[n] = masked max over t (pos);  out[E+n] = masked max over t (neg)
// ---------------------------------------------------------------------------

#define TT    8
#define DDIM  200
#define HDIM  100
#define KPAD  208           // 13 ksteps of 16 (k=200 is the bias row)
#define NPAD  112           // 14 n-frags of 8
#define BM    128
#define EMAX  65536

__device__ __align__(16) uint16_t g_A[(size_t)3 * EMAX * KPAD];          // 82 MB fp16
__device__ __align__(16) uint16_t g_B[(size_t)2 * TT * KPAD * NPAD];     // 745 KB fp16

// ---- smem layout (bytes) ----
#define OFF_OW  0                        // 8 * 112 floats = 3584
#define OFF_A   3584
#define A_ROWB  432                      // 208 k * 2B = 416, +16 pad (conflict-free)
#define A_SZ    (384 * A_ROWB)           // 165888
#define OFF_B   (OFF_A + A_SZ)           // 169472
#define B_ROWB  240                      // 112 n * 2B = 224, +16 pad (conflict-free)
#define B_SET   (64 * B_ROWB)            // 15360 per wm
#define SMEM_TOTAL (OFF_B + 2 * B_SET)   // 200192

// ---------------- asm helpers ----------------
__device__ __forceinline__ uint32_t smem_u32(const void* p) {
    uint32_t a;
    asm("{ .reg .u64 t; cvta.to.shared.u64 t, %1; cvt.u32.u64 %0, t; }" : "=r"(a) : "l"(p));
    return a;
}

#define LDSM_X4(R0,R1,R2,R3,ADDR) \
    asm volatile("ldmatrix.sync.aligned.m8n8.x4.shared.b16 {%0,%1,%2,%3}, [%4];" \
        : "=r"(R0), "=r"(R1), "=r"(R2), "=r"(R3) : "r"(ADDR))

#define LDSM_X4T(R0,R1,R2,R3,ADDR) \
    asm volatile("ldmatrix.sync.aligned.m8n8.x4.trans.shared.b16 {%0,%1,%2,%3}, [%4];" \
        : "=r"(R0), "=r"(R1), "=r"(R2), "=r"(R3) : "r"(ADDR))

#define MMA4(C, A, B0, B1) \
    asm volatile("mma.sync.aligned.m16n8k16.row.col.f32.f16.f16.f32 " \
        "{%0,%1,%2,%3}, {%4,%5,%6,%7}, {%8,%9}, {%0,%1,%2,%3};" \
        : "+f"((C)[0]), "+f"((C)[1]), "+f"((C)[2]), "+f"((C)[3]) \
        : "r"((A)[0]), "r"((A)[1]), "r"((A)[2]), "r"((A)[3]), "r"(B0), "r"(B1))

// ---------------------------------------------------------------------------
// prep A: h (fp32, 3E x 200) -> fp16, K padded to 208 (k200 = 1.0, rest 0)
// ---------------------------------------------------------------------------
__global__ void prepA_kernel(const float* __restrict__ h, int E) {
    const long gid = (long)blockIdx.x * 256 + threadIdx.x;
    const long total = (long)3 * E * 26;          // 26 groups of 8 per row
    if (gid >= total) return;
    const int  q   = (int)(gid % 26);
    const long row = gid / 26;
    const int  k0  = q * 8;
    const float* hr = h + row * DDIM;

    __align__(16) uint16_t hb[8];
    #pragma unroll
    for (int j = 0; j < 8; ++j) {
        const int k = k0 + j;
        const float v = (k < DDIM) ? hr[k] : (k == DDIM ? 1.0f : 0.0f);
        const __half x = __float2half(v);
        hb[j] = *reinterpret_cast<const uint16_t*>(&x);
    }
    *reinterpret_cast<uint4*>(g_A + (size_t)row * KPAD + k0) =
        *reinterpret_cast<uint4*>(hb);
}

// ---------------------------------------------------------------------------
// prep B: src_W/dst_W (T,200,100) + biases -> g_B[wm][t][208][112] fp16,
// k-major rows of n (for ldmatrix.trans); bias at k==200; zero padding
// ---------------------------------------------------------------------------
__global__ void prepB_kernel(const float* __restrict__ srcW, const float* __restrict__ srcb,
                             const float* __restrict__ dstW, const float* __restrict__ dstb) {
    const int gid = blockIdx.x * 256 + threadIdx.x;
    const int total = 2 * TT * KPAD * 14;
    if (gid >= total) return;
    const int nb = gid % 14;
    int rr = gid / 14;
    const int k = rr % KPAD;  rr /= KPAD;
    const int t = rr % TT;
    const int wm = rr / TT;

    const float* W  = wm ? dstW : srcW;
    const float* bb = wm ? dstb : srcb;

    __align__(16) uint16_t hb[8];
    #pragma unroll
    for (int j = 0; j < 8; ++j) {
        const int n = nb * 8 + j;
        float v = 0.0f;
        if (n < HDIM) {
            if (k < DDIM)       v = W[((size_t)t * DDIM + k) * HDIM + n];
            else if (k == DDIM) v = bb[t * HDIM + n];
        }
        const __half x = __float2half(v);
        hb[j] = *reinterpret_cast<const uint16_t*>(&x);
    }
    *reinterpret_cast<uint4*>(
        g_B + (((size_t)wm * TT + t) * KPAD + k) * NPAD + nb * 8) =
        *reinterpret_cast<uint4*>(hb);
}

// ---------------------------------------------------------------------------
// main kernel: 128 edges/block; A (3 mats, full K) staged ONCE in smem;
// B staged per (t, k-chunk). Warp w owns 16 edges across src/pos/neg.
// ---------------------------------------------------------------------------
__global__ __launch_bounds__(256, 1)
void sthn_hmma_kernel(const float* __restrict__ outW, const float* __restrict__ outb,
                      const int* __restrict__ poss, float* __restrict__ out, int E)
{
    extern __shared__ char smem[];
    const uint32_t sb = smem_u32(smem);
    const int tid = threadIdx.x;
    const int w = tid >> 5, l = tid & 31;
    const int blk = blockIdx.x;

    // ---- stage out_W (zero-padded) ----
    {
        float* sOW = reinterpret_cast<float*>(smem + OFF_OW);
        for (int i = tid; i < TT * NPAD; i += 256) {
            const int t = i / NPAD, n = i % NPAD;
            sOW[i] = (n < HDIM) ? outW[t * HDIM + n] : 0.0f;
        }
    }
    // ---- stage A once: 384 rows x 208 k (26 uint4 per row) ----
    for (int i = tid; i < 384 * 26; i += 256) {
        const int row = i / 26, q = i % 26;
        const int m = row >> 7, r = row & 127;
        // NOTE: g_A is uint16_t*, one uint4 = 8 elements -> element offset q*8
        const uint4 v = *reinterpret_cast<const uint4*>(
            g_A + ((size_t)m * E + (size_t)blk * BM + r) * KPAD + q * 8);
        // smem offset is in BYTES -> q*16
        *reinterpret_cast<uint4*>(smem + OFF_A + row * A_ROWB + q * 16) = v;
    }
    __syncthreads();

    const int lr = l & 15, lc = l >> 4;            // ldmatrix lane addressing
    const int qr = l >> 2, qc = l & 3;             // C-fragment row/col in quad
    const uint32_t a_lane = (uint32_t)((w * 16 + lr) * A_ROWB + lc * 16);
    const uint32_t b_lane = (uint32_t)(lr * B_ROWB + lc * 16);

    float bests[4] = {-1e30f, -1e30f, -1e30f, -1e30f};
    int   anys[4]  = {0, 0, 0, 0};

    for (int t = 0; t < TT; ++t) {
        float C[3][14][4];
        #pragma unroll
        for (int m = 0; m < 3; ++m)
            #pragma unroll
            for (int nf = 0; nf < 14; ++nf)
                #pragma unroll
                for (int j = 0; j < 4; ++j) C[m][nf][j] = 0.0f;

        for (int chunk = 0; chunk < 4; ++chunk) {
            const int krows = (chunk < 3) ? 64 : 16;     // k rows in this chunk
            __syncthreads();                              // B consumed by all warps
            // ---- stage B chunk: 2 sets x krows x 112 n ----
            for (int i = tid; i < 2 * krows * 14; i += 256) {
                const int set = i / (krows * 14), rem = i % (krows * 14);
                const int kr = rem / 14, q = rem % 14;
                const uint4 v = *reinterpret_cast<const uint4*>(
                    g_B + (((size_t)set * TT + t) * KPAD + chunk * 64 + kr) * NPAD + q * 8);
                *reinterpret_cast<uint4*>(smem + OFF_B + set * B_SET + kr * B_ROWB + q * 16) = v;
            }
            __syncthreads();

            const int nk = (chunk < 3) ? 4 : 1;
            for (int ks = 0; ks < nk; ++ks) {
                const uint32_t kb = (uint32_t)(chunk * 64 + ks * 16) * 2;  // byte offset in A row
                uint32_t Ah[3][4];
                #pragma unroll
                for (int m = 0; m < 3; ++m) {
                    const uint32_t aa = sb + OFF_A + (uint32_t)(m * 128 * A_ROWB)
                                        + a_lane + kb;
                    LDSM_X4(Ah[m][0], Ah[m][1], Ah[m][2], Ah[m][3], aa);
                }
                #pragma unroll
                for (int wm = 0; wm < 2; ++wm) {
                    #pragma unroll
                    for (int nf2 = 0; nf2 < 7; ++nf2) {
                        const uint32_t ba = sb + OFF_B + (uint32_t)(wm * B_SET)
                                            + (uint32_t)(ks * 16) * B_ROWB
                                            + b_lane + (uint32_t)nf2 * 32;
                        uint32_t bh[4];
                        LDSM_X4T(bh[0], bh[1], bh[2], bh[3], ba);
                        if (wm == 0) {
                            MMA4(C[0][2*nf2],   Ah[0], bh[0], bh[1]);
                            MMA4(C[0][2*nf2+1], Ah[0], bh[2], bh[3]);
                        } else {
                            #pragma unroll
                            for (int m = 1; m < 3; ++m) {
                                MMA4(C[m][2*nf2],   Ah[m], bh[0], bh[1]);
                                MMA4(C[m][2*nf2+1], Ah[m], bh[2], bh[3]);
                            }
                        }
                    }
                }
            }
        }

        // ---- epilogue: relu(src+dst) . out_W, quad reduce, masked max ----
        float pl = 0.f, ph = 0.f, nl = 0.f, nh = 0.f;
        const float* ow = reinterpret_cast<const float*>(smem + OFF_OW) + t * NPAD;
        const int col0 = 2 * qc;
        #pragma unroll
        for (int nf = 0; nf < 14; ++nf) {
            const float ow0 = ow[nf * 8 + col0];
            const float ow1 = ow[nf * 8 + col0 + 1];
            pl += fmaxf(C[0][nf][0] + C[1][nf][0], 0.f) * ow0
                + fmaxf(C[0][nf][1] + C[1][nf][1], 0.f) * ow1;
            ph += fmaxf(C[0][nf][2] + C[1][nf][2], 0.f) * ow0
                + fmaxf(C[0][nf][3] + C[1][nf][3], 0.f) * ow1;
            nl += fmaxf(C[0][nf][0] + C[2][nf][0], 0.f) * ow0
                + fmaxf(C[0][nf][1] + C[2][nf][1], 0.f) * ow1;
            nh += fmaxf(C[0][nf][2] + C[2][nf][2], 0.f) * ow0
                + fmaxf(C[0][nf][3] + C[2][nf][3], 0.f) * ow1;
        }
        #pragma unroll
        for (int off = 1; off < 4; off <<= 1) {
            pl += __shfl_xor_sync(0xffffffffu, pl, off);
            ph += __shfl_xor_sync(0xffffffffu, ph, off);
            nl += __shfl_xor_sync(0xffffffffu, nl, off);
            nh += __shfl_xor_sync(0xffffffffu, nh, off);
        }

        const float ob = __ldg(outb + t);
        const int e_lo = blk * BM + w * 16 + qr;
        const int e_hi = e_lo + 8;
        const int mpl = __ldg(poss + (size_t)e_lo * TT + t);
        const int mph = __ldg(poss + (size_t)e_hi * TT + t);
        const int mnl = __ldg(poss + ((size_t)E + e_lo) * TT + t);
        const int mnh = __ldg(poss + ((size_t)E + e_hi) * TT + t);
        if (mpl) { bests[0] = fmaxf(bests[0], pl + ob); anys[0] = 1; }
        if (mph) { bests[1] = fmaxf(bests[1], ph + ob); anys[1] = 1; }
        if (mnl) { bests[2] = fmaxf(bests[2], nl + ob); anys[2] = 1; }
        if (mnh) { bests[3] = fmaxf(bests[3], nh + ob); anys[3] = 1; }
    }

    if (qc == 0) {
        const int e_lo = blk * BM + w * 16 + qr;
        const int e_hi = e_lo + 8;
        out[e_lo]     = anys[0] ? bests[0] : 0.0f;
        out[e_hi]     = anys[1] ? bests[1] : 0.0f;
        out[E + e_lo] = anys[2] ? bests[2] : 0.0f;
        out[E + e_hi] = anys[3] ? bests[3] : 0.0f;
    }
}

// ---------------------------------------------------------------------------
extern "C" void kernel_launch(void* const* d_in, const int* in_sizes, int n_in,
                              void* d_out, int out_size)
{
    const float* h    = (const float*)d_in[0];
    const float* srcW = (const float*)d_in[1];
    const float* srcb = (const float*)d_in[2];
    const float* dstW = (const float*)d_in[3];
    const float* dstb = (const float*)d_in[4];
    const float* outW = (const float*)d_in[5];
    const float* outb = (const float*)d_in[6];
    const int*   poss = (const int*)d_in[7];
    float* out = (float*)d_out;

    const int E = in_sizes[0] / (DDIM * 3);

    {
        const long totalA = (long)3 * E * 26;
        prepA_kernel<<<(int)((totalA + 255) / 256), 256>>>(h, E);
    }
    {
        const int totalB = 2 * TT * KPAD * 14;
        prepB_kernel<<<(totalB + 255) / 256, 256>>>(srcW, srcb, dstW, dstb);
    }

    cudaFuncSetAttribute(sthn_hmma_kernel,
                         cudaFuncAttributeMaxDynamicSharedMemorySize, SMEM_TOTAL);
    sthn_hmma_kernel<<<E / BM, 256, SMEM_TOTAL>>>(outW, outb, poss, out, E);
}

// round 7
// speedup vs baseline: 6.6141x; 1.2864x over previous
#include <cuda_runtime.h>
#include <cuda_fp16.h>
#include <cstdint>

// ---------------------------------------------------------------------------
// HeteroSTHN link-prediction head via mma.sync HMMA fp16 (single pass,
// fp32 accumulate), double-buffered cp.async B pipeline, in-kernel A convert.
//
//   enc_src = h_src @ src_W + src_b   (bias folded as K row 200, A=1.0)
//   enc_dst = h_dst @ dst_W + dst_b
//   pred[n,t] = relu(enc_src + enc_dst) @ out_W[t] + out_b[t]
//   out[n] = masked max over t (pos);  out[E+n] = masked max over t (neg)
// ---------------------------------------------------------------------------

#define TT    8
#define DDIM  200
#define HDIM  100
#define KPAD  208           // 13 ksteps of 16 (k=200 is the bias row)
#define NPAD  112           // 14 n-frags of 8
#define BM    128

__device__ __align__(16) uint16_t g_B[(size_t)2 * TT * KPAD * NPAD];     // 745 KB fp16

// ---- smem layout (bytes) ----
#define OFF_OW  0                        // 8 * 112 floats = 3584
#define OFF_A   3584
#define A_ROWB  432                      // 208 k * 2B = 416, +16 pad (conflict-free)
#define A_SZ    (384 * A_ROWB)           // 165888
#define OFF_B   (OFF_A + A_SZ)           // 169472
#define B_ROWB  240                      // 112 n * 2B = 224, +16 pad (conflict-free)
#define B_SET   (32 * B_ROWB)            // 7680  (32 k-rows per chunk, per wm)
#define B_BUF   (2 * B_SET)              // 15360 per pipeline buffer
#define SMEM_TOTAL (OFF_B + 2 * B_BUF)   // 200192

#define NCHUNK  7                        // 6 x 32 + 1 x 16 k-rows
#define NCT     (TT * NCHUNK)            // 56 pipeline steps

// ---------------- asm helpers ----------------
__device__ __forceinline__ uint32_t smem_u32(const void* p) {
    uint32_t a;
    asm("{ .reg .u64 t; cvta.to.shared.u64 t, %1; cvt.u32.u64 %0, t; }" : "=r"(a) : "l"(p));
    return a;
}

#define LDSM_X4(R0,R1,R2,R3,ADDR) \
    asm volatile("ldmatrix.sync.aligned.m8n8.x4.shared.b16 {%0,%1,%2,%3}, [%4];" \
        : "=r"(R0), "=r"(R1), "=r"(R2), "=r"(R3) : "r"(ADDR))

#define LDSM_X4T(R0,R1,R2,R3,ADDR) \
    asm volatile("ldmatrix.sync.aligned.m8n8.x4.trans.shared.b16 {%0,%1,%2,%3}, [%4];" \
        : "=r"(R0), "=r"(R1), "=r"(R2), "=r"(R3) : "r"(ADDR))

#define MMA4(C, A, B0, B1) \
    asm volatile("mma.sync.aligned.m16n8k16.row.col.f32.f16.f16.f32 " \
        "{%0,%1,%2,%3}, {%4,%5,%6,%7}, {%8,%9}, {%0,%1,%2,%3};" \
        : "+f"((C)[0]), "+f"((C)[1]), "+f"((C)[2]), "+f"((C)[3]) \
        : "r"((A)[0]), "r"((A)[1]), "r"((A)[2]), "r"((A)[3]), "r"(B0), "r"(B1))

#define CP_ASYNC16(SMEM, GPTR) \
    asm volatile("cp.async.cg.shared.global [%0], [%1], 16;" :: "r"(SMEM), "l"(GPTR))
#define CP_COMMIT()  asm volatile("cp.async.commit_group;" ::: "memory")
#define CP_WAIT0()   asm volatile("cp.async.wait_group 0;" ::: "memory")

// ---------------------------------------------------------------------------
// prep B: src_W/dst_W (T,200,100) + biases -> g_B[wm][t][208][112] fp16,
// k-major rows of n (for ldmatrix.trans); bias at k==200; zero padding
// ---------------------------------------------------------------------------
__global__ void prepB_kernel(const float* __restrict__ srcW, const float* __restrict__ srcb,
                             const float* __restrict__ dstW, const float* __restrict__ dstb) {
    const int gid = blockIdx.x * 256 + threadIdx.x;
    const int total = 2 * TT * KPAD * 14;
    if (gid >= total) return;
    const int nb = gid % 14;
    int rr = gid / 14;
    const int k = rr % KPAD;  rr /= KPAD;
    const int t = rr % TT;
    const int wm = rr / TT;

    const float* W  = wm ? dstW : srcW;
    const float* bb = wm ? dstb : srcb;

    __align__(16) uint16_t hb[8];
    #pragma unroll
    for (int j = 0; j < 8; ++j) {
        const int n = nb * 8 + j;
        float v = 0.0f;
        if (n < HDIM) {
            if (k < DDIM)       v = W[((size_t)t * DDIM + k) * HDIM + n];
            else if (k == DDIM) v = bb[t * HDIM + n];
        }
        const __half x = __float2half(v);
        hb[j] = *reinterpret_cast<const uint16_t*>(&x);
    }
    *reinterpret_cast<uint4*>(
        g_B + (((size_t)wm * TT + t) * KPAD + k) * NPAD + nb * 8) =
        *reinterpret_cast<uint4*>(hb);
}

// ---------------------------------------------------------------------------
// main kernel: 128 edges/block; A converted fp32->fp16 in-kernel, staged once;
// B pipelined via double-buffered cp.async (32 k-rows per chunk).
// ---------------------------------------------------------------------------
__global__ __launch_bounds__(256, 1)
void sthn_hmma_kernel(const float* __restrict__ h,
                      const float* __restrict__ outW, const float* __restrict__ outb,
                      const int* __restrict__ poss, float* __restrict__ out, int E)
{
    extern __shared__ char smem[];
    const uint32_t sb = smem_u32(smem);
    const int tid = threadIdx.x;
    const int w = tid >> 5, l = tid & 31;
    const int blk = blockIdx.x;

    // ---- B chunk issue helper (cp.async, one commit group) ----
    auto issueB = [&](int ct, int buf) {
        const int t = ct / NCHUNK, c = ct % NCHUNK;
        const int rows = (c < 6) ? 32 : 16;
        const int nops = 2 * rows * 14;
        for (int i = tid; i < nops; i += 256) {
            const int set = i / (rows * 14), rem = i % (rows * 14);
            const int kr = rem / 14, q = rem % 14;
            const uint16_t* src = g_B
                + (((size_t)set * TT + t) * KPAD + c * 32 + kr) * NPAD + q * 8;
            const uint32_t dst = sb + OFF_B + (uint32_t)(buf * B_BUF + set * B_SET
                                 + kr * B_ROWB + q * 16);
            CP_ASYNC16(dst, src);
        }
        CP_COMMIT();
    };

    // ---- stage out_W (zero-padded) ----
    {
        float* sOW = reinterpret_cast<float*>(smem + OFF_OW);
        for (int i = tid; i < TT * NPAD; i += 256) {
            const int t = i / NPAD, n = i % NPAD;
            sOW[i] = (n < HDIM) ? outW[t * HDIM + n] : 0.0f;
        }
    }
    // ---- kick off first B chunk before A conversion (overlap) ----
    issueB(0, 0);

    // ---- stage A once: fp32 h -> fp16, 384 rows x 26 groups of 8 k ----
    for (int i = tid; i < 384 * 26; i += 256) {
        const int row = i / 26, q = i % 26;
        const int m = row >> 7, r = row & 127;
        __align__(16) uint16_t hb[8];
        if (q < 25) {                       // k 0..199 straight from h
            const float* hr = h + ((size_t)m * E + (size_t)blk * BM + r) * DDIM + q * 8;
            const float4 f0 = *reinterpret_cast<const float4*>(hr);
            const float4 f1 = *reinterpret_cast<const float4*>(hr + 4);
            const __half2 h0 = __floats2half2_rn(f0.x, f0.y);
            const __half2 h1 = __floats2half2_rn(f0.z, f0.w);
            const __half2 h2 = __floats2half2_rn(f1.x, f1.y);
            const __half2 h3 = __floats2half2_rn(f1.z, f1.w);
            *reinterpret_cast<__half2*>(hb + 0) = h0;
            *reinterpret_cast<__half2*>(hb + 2) = h1;
            *reinterpret_cast<__half2*>(hb + 4) = h2;
            *reinterpret_cast<__half2*>(hb + 6) = h3;
        } else {                             // k 200 = bias 1.0, 201..207 = 0
            hb[0] = 0x3C00; hb[1] = 0; hb[2] = 0; hb[3] = 0;
            hb[4] = 0; hb[5] = 0; hb[6] = 0; hb[7] = 0;
        }
        *reinterpret_cast<uint4*>(smem + OFF_A + row * A_ROWB + q * 16) =
            *reinterpret_cast<uint4*>(hb);
    }

    const int lr = l & 15, lc = l >> 4;            // ldmatrix lane addressing
    const int qr = l >> 2, qc = l & 3;             // C-fragment row/col in quad
    const uint32_t a_lane = (uint32_t)((w * 16 + lr) * A_ROWB + lc * 16);
    const uint32_t b_lane = (uint32_t)(lr * B_ROWB + lc * 16);

    float bests[4] = {-1e30f, -1e30f, -1e30f, -1e30f};
    int   anys[4]  = {0, 0, 0, 0};

    float C[3][14][4];
    #pragma unroll
    for (int m = 0; m < 3; ++m)
        #pragma unroll
        for (int nf = 0; nf < 14; ++nf)
            #pragma unroll
            for (int j = 0; j < 4; ++j) C[m][nf][j] = 0.0f;

    for (int ct = 0; ct < NCT; ++ct) {
        const int t = ct / NCHUNK, c = ct % NCHUNK;
        const int buf = ct & 1;

        CP_WAIT0();                 // current chunk's B landed
        __syncthreads();            // visible to all warps; prev MMAs on other buf done

        if (ct + 1 < NCT) issueB(ct + 1, buf ^ 1);   // next chunk flies during MMA

        const int nk = (c < 6) ? 2 : 1;
        const uint32_t bbase = sb + OFF_B + (uint32_t)(buf * B_BUF);
        for (int ks = 0; ks < nk; ++ks) {
            const uint32_t kb = (uint32_t)(c * 32 + ks * 16) * 2;  // byte off in A row
            uint32_t Ah[3][4];
            #pragma unroll
            for (int m = 0; m < 3; ++m) {
                const uint32_t aa = sb + OFF_A + (uint32_t)(m * 128 * A_ROWB)
                                    + a_lane + kb;
                LDSM_X4(Ah[m][0], Ah[m][1], Ah[m][2], Ah[m][3], aa);
            }
            #pragma unroll
            for (int wm = 0; wm < 2; ++wm) {
                #pragma unroll
                for (int nf2 = 0; nf2 < 7; ++nf2) {
                    const uint32_t ba = bbase + (uint32_t)(wm * B_SET)
                                        + (uint32_t)(ks * 16) * B_ROWB
                                        + b_lane + (uint32_t)nf2 * 32;
                    uint32_t bh[4];
                    LDSM_X4T(bh[0], bh[1], bh[2], bh[3], ba);
                    if (wm == 0) {
                        MMA4(C[0][2*nf2],   Ah[0], bh[0], bh[1]);
                        MMA4(C[0][2*nf2+1], Ah[0], bh[2], bh[3]);
                    } else {
                        #pragma unroll
                        for (int m = 1; m < 3; ++m) {
                            MMA4(C[m][2*nf2],   Ah[m], bh[0], bh[1]);
                            MMA4(C[m][2*nf2+1], Ah[m], bh[2], bh[3]);
                        }
                    }
                }
            }
        }

        if (c == NCHUNK - 1) {
            // ---- epilogue for t: relu(src+dst).out_W, quad reduce, masked max ----
            float pl = 0.f, ph = 0.f, nl = 0.f, nh = 0.f;
            const float* ow = reinterpret_cast<const float*>(smem + OFF_OW) + t * NPAD;
            const int col0 = 2 * qc;
            #pragma unroll
            for (int nf = 0; nf < 14; ++nf) {
                const float ow0 = ow[nf * 8 + col0];
                const float ow1 = ow[nf * 8 + col0 + 1];
                pl += fmaxf(C[0][nf][0] + C[1][nf][0], 0.f) * ow0
                    + fmaxf(C[0][nf][1] + C[1][nf][1], 0.f) * ow1;
                ph += fmaxf(C[0][nf][2] + C[1][nf][2], 0.f) * ow0
                    + fmaxf(C[0][nf][3] + C[1][nf][3], 0.f) * ow1;
                nl += fmaxf(C[0][nf][0] + C[2][nf][0], 0.f) * ow0
                    + fmaxf(C[0][nf][1] + C[2][nf][1], 0.f) * ow1;
                nh += fmaxf(C[0][nf][2] + C[2][nf][2], 0.f) * ow0
                    + fmaxf(C[0][nf][3] + C[2][nf][3], 0.f) * ow1;
            }
            #pragma unroll
            for (int off = 1; off < 4; off <<= 1) {
                pl += __shfl_xor_sync(0xffffffffu, pl, off);
                ph += __shfl_xor_sync(0xffffffffu, ph, off);
                nl += __shfl_xor_sync(0xffffffffu, nl, off);
                nh += __shfl_xor_sync(0xffffffffu, nh, off);
            }

            const float ob = __ldg(outb + t);
            const int e_lo = blk * BM + w * 16 + qr;
            const int e_hi = e_lo + 8;
            const int mpl = __ldg(poss + (size_t)e_lo * TT + t);
            const int mph = __ldg(poss + (size_t)e_hi * TT + t);
            const int mnl = __ldg(poss + ((size_t)E + e_lo) * TT + t);
            const int mnh = __ldg(poss + ((size_t)E + e_hi) * TT + t);
            if (mpl) { bests[0] = fmaxf(bests[0], pl + ob); anys[0] = 1; }
            if (mph) { bests[1] = fmaxf(bests[1], ph + ob); anys[1] = 1; }
            if (mnl) { bests[2] = fmaxf(bests[2], nl + ob); anys[2] = 1; }
            if (mnh) { bests[3] = fmaxf(bests[3], nh + ob); anys[3] = 1; }

            #pragma unroll
            for (int m = 0; m < 3; ++m)
                #pragma unroll
                for (int nf = 0; nf < 14; ++nf)
                    #pragma unroll
                    for (int j = 0; j < 4; ++j) C[m][nf][j] = 0.0f;
        }
    }

    if (qc == 0) {
        const int e_lo = blk * BM + w * 16 + qr;
        const int e_hi = e_lo + 8;
        out[e_lo]     = anys[0] ? bests[0] : 0.0f;
        out[e_hi]     = anys[1] ? bests[1] : 0.0f;
        out[E + e_lo] = anys[2] ? bests[2] : 0.0f;
        out[E + e_hi] = anys[3] ? bests[3] : 0.0f;
    }
}

// ---------------------------------------------------------------------------
extern "C" void kernel_launch(void* const* d_in, const int* in_sizes, int n_in,
                              void* d_out, int out_size)
{
    const float* h    = (const float*)d_in[0];
    const float* srcW = (const float*)d_in[1];
    const float* srcb = (const float*)d_in[2];
    const float* dstW = (const float*)d_in[3];
    const float* dstb = (const float*)d_in[4];
    const float* outW = (const float*)d_in[5];
    const float* outb = (const float*)d_in[6];
    const int*   poss = (const int*)d_in[7];
    float* out = (float*)d_out;

    const int E = in_sizes[0] / (DDIM * 3);

    {
        const int totalB = 2 * TT * KPAD * 14;
        prepB_kernel<<<(totalB + 255) / 256, 256>>>(srcW, srcb, dstW, dstb);
    }

    cudaFuncSetAttribute(sthn_hmma_kernel,
                         cudaFuncAttributeMaxDynamicSharedMemorySize, SMEM_TOTAL);
    sthn_hmma_kernel<<<E / BM, 256, SMEM_TOTAL>>>(h, outW, outb, poss, out, E);
}

// round 8
// speedup vs baseline: 7.2982x; 1.1034x over previous
#include <cuda_runtime.h>
#include <cuda_fp16.h>
#include <cstdint>

// ---------------------------------------------------------------------------
// HeteroSTHN link-prediction head via mma.sync HMMA fp16 (single pass,
// fp32 accumulate), double-buffered cp.async B pipeline, in-kernel A convert.
// 512 threads: warp (mw, nw) owns m-rows [mw*16,mw*16+16) x n-half nw*64.
//
//   enc_src = h_src @ src_W + src_b   (bias folded as K row 200, A=1.0)
//   enc_dst = h_dst @ dst_W + dst_b
//   pred[n,t] = relu(enc_src + enc_dst) @ out_W[t] + out_b[t]
//   out[n] = masked max over t (pos);  out[E+n] = masked max over t (neg)
// ---------------------------------------------------------------------------

#define TT    8
#define DDIM  200
#define HDIM  100
#define KPAD  208           // 13 ksteps of 16 (k=200 is the bias row)
#define NPAD  128           // 16 n-frags of 8; 8 LDSM groups of 16
#define BM    128
#define NTHR  512

__device__ __align__(16) uint16_t g_B[(size_t)2 * TT * KPAD * NPAD];     // 1.7 MB fp16

// ---- smem layout (bytes) ----
#define OFF_OW  0                        // 8 * 128 floats = 4096
#define OFF_RED 4096                     // 8 mw * 8 qr * 4 floats = 1024
#define OFF_A   5120
#define A_ROWB  432                      // 208 k * 2B = 416, +16 pad (conflict-free)
#define A_SZ    (384 * A_ROWB)           // 165888
#define OFF_B   (OFF_A + A_SZ)           // 171008
#define B_ROWB  272                      // 128 n * 2B = 256, +16 pad (conflict-free)
#define B_SET   (32 * B_ROWB)            // 8704  (32 k-rows per chunk, per wm)
#define B_BUF   (2 * B_SET)              // 17408 per pipeline buffer
#define SMEM_TOTAL (OFF_B + 2 * B_BUF)   // 205824

#define NCHUNK  7                        // 6 x 32 + 1 x 16 k-rows
#define NCT     (TT * NCHUNK)            // 56 pipeline steps

// ---------------- asm helpers ----------------
__device__ __forceinline__ uint32_t smem_u32(const void* p) {
    uint32_t a;
    asm("{ .reg .u64 t; cvta.to.shared.u64 t, %1; cvt.u32.u64 %0, t; }" : "=r"(a) : "l"(p));
    return a;
}

#define LDSM_X4(R0,R1,R2,R3,ADDR) \
    asm volatile("ldmatrix.sync.aligned.m8n8.x4.shared.b16 {%0,%1,%2,%3}, [%4];" \
        : "=r"(R0), "=r"(R1), "=r"(R2), "=r"(R3) : "r"(ADDR))

#define LDSM_X4T(R0,R1,R2,R3,ADDR) \
    asm volatile("ldmatrix.sync.aligned.m8n8.x4.trans.shared.b16 {%0,%1,%2,%3}, [%4];" \
        : "=r"(R0), "=r"(R1), "=r"(R2), "=r"(R3) : "r"(ADDR))

#define MMA4(C, A, B0, B1) \
    asm volatile("mma.sync.aligned.m16n8k16.row.col.f32.f16.f16.f32 " \
        "{%0,%1,%2,%3}, {%4,%5,%6,%7}, {%8,%9}, {%0,%1,%2,%3};" \
        : "+f"((C)[0]), "+f"((C)[1]), "+f"((C)[2]), "+f"((C)[3]) \
        : "r"((A)[0]), "r"((A)[1]), "r"((A)[2]), "r"((A)[3]), "r"(B0), "r"(B1))

#define CP_ASYNC16(SMEM, GPTR) \
    asm volatile("cp.async.cg.shared.global [%0], [%1], 16;" :: "r"(SMEM), "l"(GPTR))
#define CP_COMMIT()  asm volatile("cp.async.commit_group;" ::: "memory")
#define CP_WAIT0()   asm volatile("cp.async.wait_group 0;" ::: "memory")

// ---------------------------------------------------------------------------
// prep B: src_W/dst_W (T,200,100) + biases -> g_B[wm][t][208][128] fp16,
// k-major rows of n (for ldmatrix.trans); bias at k==200; zero padding
// ---------------------------------------------------------------------------
__global__ void prepB_kernel(const float* __restrict__ srcW, const float* __restrict__ srcb,
                             const float* __restrict__ dstW, const float* __restrict__ dstb) {
    const int gid = blockIdx.x * 256 + threadIdx.x;
    const int total = 2 * TT * KPAD * 16;
    if (gid >= total) return;
    const int nb = gid % 16;
    int rr = gid / 16;
    const int k = rr % KPAD;  rr /= KPAD;
    const int t = rr % TT;
    const int wm = rr / TT;

    const float* W  = wm ? dstW : srcW;
    const float* bb = wm ? dstb : srcb;

    __align__(16) uint16_t hb[8];
    #pragma unroll
    for (int j = 0; j < 8; ++j) {
        const int n = nb * 8 + j;
        float v = 0.0f;
        if (n < HDIM) {
            if (k < DDIM)       v = W[((size_t)t * DDIM + k) * HDIM + n];
            else if (k == DDIM) v = bb[t * HDIM + n];
        }
        const __half x = __float2half(v);
        hb[j] = *reinterpret_cast<const uint16_t*>(&x);
    }
    *reinterpret_cast<uint4*>(
        g_B + (((size_t)wm * TT + t) * KPAD + k) * NPAD + nb * 8) =
        *reinterpret_cast<uint4*>(hb);
}

// ---------------------------------------------------------------------------
// main kernel
// ---------------------------------------------------------------------------
__global__ __launch_bounds__(NTHR, 1)
void sthn_hmma_kernel(const float* __restrict__ h,
                      const float* __restrict__ outW, const float* __restrict__ outb,
                      const int* __restrict__ poss, float* __restrict__ out, int E)
{
    extern __shared__ char smem[];
    const uint32_t sb = smem_u32(smem);
    const int tid = threadIdx.x;
    const int w = tid >> 5, l = tid & 31;
    const int mw = w >> 1, nw = w & 1;
    const int blk = blockIdx.x;

    // ---- B chunk issue helper (cp.async, one commit group) ----
    auto issueB = [&](int ct, int buf) {
        const int t = ct / NCHUNK, c = ct % NCHUNK;
        const int rows = (c < 6) ? 32 : 16;
        const int nops = 2 * rows * 16;
        for (int i = tid; i < nops; i += NTHR) {
            const int set = i / (rows * 16), rem = i % (rows * 16);
            const int kr = rem / 16, q = rem % 16;
            const uint16_t* src = g_B
                + (((size_t)set * TT + t) * KPAD + c * 32 + kr) * NPAD + q * 8;
            const uint32_t dst = sb + OFF_B + (uint32_t)(buf * B_BUF + set * B_SET
                                 + kr * B_ROWB + q * 16);
            CP_ASYNC16(dst, src);
        }
        CP_COMMIT();
    };

    // ---- stage out_W (zero-padded) ----
    {
        float* sOW = reinterpret_cast<float*>(smem + OFF_OW);
        for (int i = tid; i < TT * NPAD; i += NTHR) {
            const int t = i / NPAD, n = i % NPAD;
            sOW[i] = (n < HDIM) ? outW[t * HDIM + n] : 0.0f;
        }
    }
    // ---- kick off first B chunk before A conversion (overlap) ----
    issueB(0, 0);

    // ---- stage A once: fp32 h -> fp16, 384 rows x 26 groups of 8 k ----
    for (int i = tid; i < 384 * 26; i += NTHR) {
        const int row = i / 26, q = i % 26;
        const int m = row >> 7, r = row & 127;
        __align__(16) uint16_t hb[8];
        if (q < 25) {
            const float* hr = h + ((size_t)m * E + (size_t)blk * BM + r) * DDIM + q * 8;
            const float4 f0 = *reinterpret_cast<const float4*>(hr);
            const float4 f1 = *reinterpret_cast<const float4*>(hr + 4);
            *reinterpret_cast<__half2*>(hb + 0) = __floats2half2_rn(f0.x, f0.y);
            *reinterpret_cast<__half2*>(hb + 2) = __floats2half2_rn(f0.z, f0.w);
            *reinterpret_cast<__half2*>(hb + 4) = __floats2half2_rn(f1.x, f1.y);
            *reinterpret_cast<__half2*>(hb + 6) = __floats2half2_rn(f1.z, f1.w);
        } else {                             // k 200 = bias 1.0, 201..207 = 0
            hb[0] = 0x3C00; hb[1] = 0; hb[2] = 0; hb[3] = 0;
            hb[4] = 0; hb[5] = 0; hb[6] = 0; hb[7] = 0;
        }
        *reinterpret_cast<uint4*>(smem + OFF_A + row * A_ROWB + q * 16) =
            *reinterpret_cast<uint4*>(hb);
    }

    const int lr = l & 15, lc = l >> 4;            // ldmatrix lane addressing
    const int qr = l >> 2, qc = l & 3;             // C-fragment row/col in quad
    const uint32_t a_lane = (uint32_t)((mw * 16 + lr) * A_ROWB + lc * 16);
    const uint32_t b_lane = (uint32_t)(lr * B_ROWB + lc * 16);

    float bests[4] = {-1e30f, -1e30f, -1e30f, -1e30f};
    int   anys[4]  = {0, 0, 0, 0};

    // C[m][local nfrag 0..7][4]; this warp's n-cols = nw*64 + nf*8
    float C[3][8][4];
    #pragma unroll
    for (int m = 0; m < 3; ++m)
        #pragma unroll
        for (int nf = 0; nf < 8; ++nf)
            #pragma unroll
            for (int j = 0; j < 4; ++j) C[m][nf][j] = 0.0f;

    float* sRED = reinterpret_cast<float*>(smem + OFF_RED);

    for (int ct = 0; ct < NCT; ++ct) {
        const int t = ct / NCHUNK, c = ct % NCHUNK;
        const int buf = ct & 1;

        CP_WAIT0();
        __syncthreads();

        if (ct + 1 < NCT) issueB(ct + 1, buf ^ 1);

        const int nk = (c < 6) ? 2 : 1;
        const uint32_t bbase = sb + OFF_B + (uint32_t)(buf * B_BUF);
        for (int ks = 0; ks < nk; ++ks) {
            const uint32_t kb = (uint32_t)(c * 32 + ks * 16) * 2;
            uint32_t Ah[3][4];
            #pragma unroll
            for (int m = 0; m < 3; ++m) {
                const uint32_t aa = sb + OFF_A + (uint32_t)(m * 128 * A_ROWB)
                                    + a_lane + kb;
                LDSM_X4(Ah[m][0], Ah[m][1], Ah[m][2], Ah[m][3], aa);
            }
            const uint32_t brow = bbase + (uint32_t)(ks * 16) * B_ROWB + b_lane
                                  + (uint32_t)(nw * 4) * 32;
            #pragma unroll
            for (int g = 0; g < 4; ++g) {
                uint32_t b0[4], b1[4];
                LDSM_X4T(b0[0], b0[1], b0[2], b0[3], brow + (uint32_t)g * 32);           // srcW
                LDSM_X4T(b1[0], b1[1], b1[2], b1[3], brow + (uint32_t)g * 32 + B_SET);   // dstW
                MMA4(C[0][2*g],   Ah[0], b0[0], b0[1]);
                MMA4(C[0][2*g+1], Ah[0], b0[2], b0[3]);
                MMA4(C[1][2*g],   Ah[1], b1[0], b1[1]);
                MMA4(C[1][2*g+1], Ah[1], b1[2], b1[3]);
                MMA4(C[2][2*g],   Ah[2], b1[0], b1[1]);
                MMA4(C[2][2*g+1], Ah[2], b1[2], b1[3]);
            }
        }

        if (c == NCHUNK - 1) {
            // ---- epilogue for t ----
            float pl = 0.f, ph = 0.f, nl = 0.f, nh = 0.f;
            const float* ow = reinterpret_cast<const float*>(smem + OFF_OW)
                              + t * NPAD + nw * 64;
            const int col0 = 2 * qc;
            #pragma unroll
            for (int nf = 0; nf < 8; ++nf) {
                const float ow0 = ow[nf * 8 + col0];
                const float ow1 = ow[nf * 8 + col0 + 1];
                pl += fmaxf(C[0][nf][0] + C[1][nf][0], 0.f) * ow0
                    + fmaxf(C[0][nf][1] + C[1][nf][1], 0.f) * ow1;
                ph += fmaxf(C[0][nf][2] + C[1][nf][2], 0.f) * ow0
                    + fmaxf(C[0][nf][3] + C[1][nf][3], 0.f) * ow1;
                nl += fmaxf(C[0][nf][0] + C[2][nf][0], 0.f) * ow0
                    + fmaxf(C[0][nf][1] + C[2][nf][1], 0.f) * ow1;
                nh += fmaxf(C[0][nf][2] + C[2][nf][2], 0.f) * ow0
                    + fmaxf(C[0][nf][3] + C[2][nf][3], 0.f) * ow1;
            }
            #pragma unroll
            for (int off = 1; off < 4; off <<= 1) {
                pl += __shfl_xor_sync(0xffffffffu, pl, off);
                ph += __shfl_xor_sync(0xffffffffu, ph, off);
                nl += __shfl_xor_sync(0xffffffffu, nl, off);
                nh += __shfl_xor_sync(0xffffffffu, nh, off);
            }

            if (nw == 0 && qc == 0) {
                float* dst = sRED + (mw * 8 + qr) * 4;
                dst[0] = pl; dst[1] = ph; dst[2] = nl; dst[3] = nh;
            }
            __syncthreads();
            if (nw == 1 && qc == 0) {
                const float* ptn = sRED + (mw * 8 + qr) * 4;
                const float tpl = pl + ptn[0];
                const float tph = ph + ptn[1];
                const float tnl = nl + ptn[2];
                const float tnh = nh + ptn[3];

                const float ob = __ldg(outb + t);
                const int e_lo = blk * BM + mw * 16 + qr;
                const int e_hi = e_lo + 8;
                const int mpl = __ldg(poss + (size_t)e_lo * TT + t);
                const int mph = __ldg(poss + (size_t)e_hi * TT + t);
                const int mnl = __ldg(poss + ((size_t)E + e_lo) * TT + t);
                const int mnh = __ldg(poss + ((size_t)E + e_hi) * TT + t);
                if (mpl) { bests[0] = fmaxf(bests[0], tpl + ob); anys[0] = 1; }
                if (mph) { bests[1] = fmaxf(bests[1], tph + ob); anys[1] = 1; }
                if (mnl) { bests[2] = fmaxf(bests[2], tnl + ob); anys[2] = 1; }
                if (mnh) { bests[3] = fmaxf(bests[3], tnh + ob); anys[3] = 1; }
            }

            #pragma unroll
            for (int m = 0; m < 3; ++m)
                #pragma unroll
                for (int nf = 0; nf < 8; ++nf)
                    #pragma unroll
                    for (int j = 0; j < 4; ++j) C[m][nf][j] = 0.0f;
        }
    }

    if (nw == 1 && qc == 0) {
        const int e_lo = blk * BM + mw * 16 + qr;
        const int e_hi = e_lo + 8;
        out[e_lo]     = anys[0] ? bests[0] : 0.0f;
        out[e_hi]     = anys[1] ? bests[1] : 0.0f;
        out[E + e_lo] = anys[2] ? bests[2] : 0.0f;
        out[E + e_hi] = anys[3] ? bests[3] : 0.0f;
    }
}

// ---------------------------------------------------------------------------
extern "C" void kernel_launch(void* const* d_in, const int* in_sizes, int n_in,
                              void* d_out, int out_size)
{
    const float* h    = (const float*)d_in[0];
    const float* srcW = (const float*)d_in[1];
    const float* srcb = (const float*)d_in[2];
    const float* dstW = (const float*)d_in[3];
    const float* dstb = (const float*)d_in[4];
    const float* outW = (const float*)d_in[5];
    const float* outb = (const float*)d_in[6];
    const int*   poss = (const int*)d_in[7];
    float* out = (float*)d_out;

    const int E = in_sizes[0] / (DDIM * 3);

    {
        const int totalB = 2 * TT * KPAD * 16;
        prepB_kernel<<<(totalB + 255) / 256, 256>>>(srcW, srcb, dstW, dstb);
    }

    cudaFuncSetAttribute(sthn_hmma_kernel,
                         cudaFuncAttributeMaxDynamicSharedMemorySize, SMEM_TOTAL);
    sthn_hmma_kernel<<<E / BM, NTHR, SMEM_TOTAL>>>(h, outW, outb, poss, out, E);
}